// round 8
// baseline (speedup 1.0000x reference)
#include <cuda_runtime.h>
#include <cstdint>

// SSM selective scan: Bsz=2, Dm=1536, L=2048, N=16 (fp32).
// R5 mapping: 1 lane per (seq, n): 16 lanes/sequence, 2 sequences/warp,
// 1536 warps total. B/C staged block-wide through smem (coalesced LDG ->
// conflict-free LDS), y buffered in smem, fused (y+x*D)*silu(z) epilogue
// per TBUF tile.

#define LOG2E 1.4426950408889634f

static constexpr int Bsz = 2;
static constexpr int Dm  = 1536;
static constexpr int L   = 2048;
static constexpr int Nst = 16;

static constexpr int TBUF = 64;                 // timesteps per tile
static constexpr int SN   = 17;                 // smem tile row stride (banks)
static constexpr int WARPS_PER_BLOCK = 4;
static constexpr int THREADS = WARPS_PER_BLOCK * 32;   // 128
static constexpr int SEQ_PER_BLOCK = WARPS_PER_BLOCK * 2;  // 8
static constexpr int NSEQ = Bsz * Dm;                      // 3072
static constexpr int NBLOCKS = NSEQ / SEQ_PER_BLOCK;       // 384

__device__ __forceinline__ float ex2f(float v) {
    float r;
    asm("ex2.approx.ftz.f32 %0, %1;" : "=f"(r) : "f"(v));
    return r;
}
__device__ __forceinline__ float rcpf(float v) {
    float r;
    asm("rcp.approx.ftz.f32 %0, %1;" : "=f"(r) : "f"(v));
    return r;
}

union F4 { float4 v; float a[4]; };

__global__ __launch_bounds__(THREADS) void ssm_scan_kernel(
    const float* __restrict__ x,
    const float* __restrict__ delta,
    const float* __restrict__ A,
    const float* __restrict__ Bm,
    const float* __restrict__ Cm,
    const float* __restrict__ Dv,
    const float* __restrict__ z,
    float* __restrict__ out)
{
    __shared__ float sB[TBUF * SN];                     // [t][n], stride 17
    __shared__ float sC[TBUF * SN];
    __shared__ float ybuf[SEQ_PER_BLOCK][TBUF + 4];     // rows 16B-aligned

    const int tid  = threadIdx.x;
    const int warp = tid >> 5;
    const int lane = tid & 31;
    const int sg   = lane >> 4;      // sequence within warp (0/1)
    const int n    = lane & 15;      // state index

    const int seqBlock = blockIdx.x * SEQ_PER_BLOCK;
    const int seq = seqBlock + warp * 2 + sg;  // 0..3071
    const int b   = seq / Dm;                  // same for whole block (8 | 1536)
    const int d   = seq % Dm;
    const int yrow = warp * 2 + sg;

    const size_t rowOff = ((size_t)b * Dm + d) * L;
    const float* xp = x     + rowOff;
    const float* dp = delta + rowOff;
    const float* zp = z     + rowOff;
    float*       op = out   + rowOff;

    const float* Bg = Bm + (size_t)b * Nst * L;
    const float* Cg = Cm + (size_t)b * Nst * L;

    // Pre-scale A by log2(e): exp(delta*A) = ex2(delta*Apre)
    const float Apn = A[d * Nst + n] * LOG2E;
    const float Dd  = Dv[d];

    float h = 0.f;

    for (int tbase = 0; tbase < L; tbase += TBUF) {
        // ---- stage B/C tile [TBUF t x 16 n] into smem, coalesced ----
        #pragma unroll
        for (int i = 0; i < 2; ++i) {
            const int f4   = tid + i * THREADS;   // 0..255
            const int nn   = f4 >> 4;             // 0..15
            const int t4p  = f4 & 15;             // 0..15 (float4 within row)
            F4 bv, cv;
            bv.v = *(const float4*)(Bg + (size_t)nn * L + tbase + t4p * 4);
            cv.v = *(const float4*)(Cg + (size_t)nn * L + tbase + t4p * 4);
            #pragma unroll
            for (int k2 = 0; k2 < 4; ++k2) {
                sB[(t4p * 4 + k2) * SN + nn] = bv.a[k2];
                sC[(t4p * 4 + k2) * SN + nn] = cv.a[k2];
            }
        }
        __syncthreads();

        // ---- scan phase over TBUF timesteps ----
        #pragma unroll 4
        for (int t4 = 0; t4 < TBUF; t4 += 4) {
            F4 d4, x4;
            d4.v = *(const float4*)(dp + tbase + t4);   // broadcast within seq group
            x4.v = *(const float4*)(xp + tbase + t4);

            #pragma unroll
            for (int k = 0; k < 4; ++k) {
                const float dt  = d4.a[k];
                const float dxv = dt * x4.a[k];
                const float e   = ex2f(dt * Apn);
                const float bb  = sB[(t4 + k) * SN + n];
                const float cc  = sC[(t4 + k) * SN + n];
                h = fmaf(e, h, dxv * bb);
                float p = h * cc;
                // reduce over 16 state lanes
                p += __shfl_xor_sync(0xffffffffu, p, 1);
                p += __shfl_xor_sync(0xffffffffu, p, 2);
                p += __shfl_xor_sync(0xffffffffu, p, 4);
                p += __shfl_xor_sync(0xffffffffu, p, 8);
                if (n == 0) ybuf[yrow][t4 + k] = p;
            }
        }
        __syncwarp();

        // ---- epilogue: out = (y + x*D) * silu(z), one float4 per lane ----
        {
            const int tt = tbase + n * 4;     // lane covers 4 timesteps of its seq
            F4 y4, xx4, zz4, o4;
            y4.v  = *(const float4*)&ybuf[yrow][n * 4];
            xx4.v = *(const float4*)(xp + tt);
            zz4.v = *(const float4*)(zp + tt);
            #pragma unroll
            for (int k = 0; k < 4; ++k) {
                const float zv  = zz4.a[k];
                const float sig = rcpf(1.f + ex2f(zv * (-LOG2E)));
                const float yv  = fmaf(xx4.a[k], Dd, y4.a[k]);
                o4.a[k] = yv * zv * sig;
            }
            *(float4*)(op + tt) = o4.v;
        }
        __syncthreads();   // protect sB/sC (and ybuf) before next tile
    }
}

extern "C" void kernel_launch(void* const* d_in, const int* in_sizes, int n_in,
                              void* d_out, int out_size)
{
    const float* x     = (const float*)d_in[0];
    const float* delta = (const float*)d_in[1];
    const float* A     = (const float*)d_in[2];
    const float* Bm    = (const float*)d_in[3];
    const float* Cm    = (const float*)d_in[4];
    const float* Dv    = (const float*)d_in[5];
    const float* z     = (const float*)d_in[6];
    float* out = (float*)d_out;

    ssm_scan_kernel<<<NBLOCKS, THREADS>>>(x, delta, A, Bm, Cm, Dv, z, out);
}

// round 10
// speedup vs baseline: 1.4910x; 1.4910x over previous
#include <cuda_runtime.h>
#include <cstdint>

// SSM selective scan: Bsz=2, Dm=1536, L=2048, N=16 (fp32).
// R5 mapping: 1 lane per (seq, n): 16 lanes/sequence, 2 sequences/warp,
// 1536 warps total. B/C staged block-wide through smem (coalesced LDG ->
// conflict-free LDS), y buffered in smem, fused (y+x*D)*silu(z) epilogue
// per TBUF tile.

#define LOG2E 1.4426950408889634f

static constexpr int Bsz = 2;
static constexpr int Dm  = 1536;
static constexpr int L   = 2048;
static constexpr int Nst = 16;

static constexpr int TBUF = 64;                 // timesteps per tile
static constexpr int SN   = 17;                 // smem tile row stride (banks)
static constexpr int WARPS_PER_BLOCK = 4;
static constexpr int THREADS = WARPS_PER_BLOCK * 32;   // 128
static constexpr int SEQ_PER_BLOCK = WARPS_PER_BLOCK * 2;  // 8
static constexpr int NSEQ = Bsz * Dm;                      // 3072
static constexpr int NBLOCKS = NSEQ / SEQ_PER_BLOCK;       // 384

__device__ __forceinline__ float ex2f(float v) {
    float r;
    asm("ex2.approx.ftz.f32 %0, %1;" : "=f"(r) : "f"(v));
    return r;
}
__device__ __forceinline__ float rcpf(float v) {
    float r;
    asm("rcp.approx.ftz.f32 %0, %1;" : "=f"(r) : "f"(v));
    return r;
}

union F4 { float4 v; float a[4]; };

__global__ __launch_bounds__(THREADS) void ssm_scan_kernel(
    const float* __restrict__ x,
    const float* __restrict__ delta,
    const float* __restrict__ A,
    const float* __restrict__ Bm,
    const float* __restrict__ Cm,
    const float* __restrict__ Dv,
    const float* __restrict__ z,
    float* __restrict__ out)
{
    __shared__ float sB[TBUF * SN];                     // [t][n], stride 17
    __shared__ float sC[TBUF * SN];
    __shared__ float ybuf[SEQ_PER_BLOCK][TBUF + 4];     // rows 16B-aligned

    const int tid  = threadIdx.x;
    const int warp = tid >> 5;
    const int lane = tid & 31;
    const int sg   = lane >> 4;      // sequence within warp (0/1)
    const int n    = lane & 15;      // state index

    const int seqBlock = blockIdx.x * SEQ_PER_BLOCK;
    const int seq = seqBlock + warp * 2 + sg;  // 0..3071
    const int b   = seq / Dm;                  // same for whole block (8 | 1536)
    const int d   = seq % Dm;
    const int yrow = warp * 2 + sg;

    const size_t rowOff = ((size_t)b * Dm + d) * L;
    const float* xp = x     + rowOff;
    const float* dp = delta + rowOff;
    const float* zp = z     + rowOff;
    float*       op = out   + rowOff;

    const float* Bg = Bm + (size_t)b * Nst * L;
    const float* Cg = Cm + (size_t)b * Nst * L;

    // Pre-scale A by log2(e): exp(delta*A) = ex2(delta*Apre)
    const float Apn = A[d * Nst + n] * LOG2E;
    const float Dd  = Dv[d];

    float h = 0.f;

    for (int tbase = 0; tbase < L; tbase += TBUF) {
        // ---- stage B/C tile [TBUF t x 16 n] into smem, coalesced ----
        #pragma unroll
        for (int i = 0; i < 2; ++i) {
            const int f4   = tid + i * THREADS;   // 0..255
            const int nn   = f4 >> 4;             // 0..15
            const int t4p  = f4 & 15;             // 0..15 (float4 within row)
            F4 bv, cv;
            bv.v = *(const float4*)(Bg + (size_t)nn * L + tbase + t4p * 4);
            cv.v = *(const float4*)(Cg + (size_t)nn * L + tbase + t4p * 4);
            #pragma unroll
            for (int k2 = 0; k2 < 4; ++k2) {
                sB[(t4p * 4 + k2) * SN + nn] = bv.a[k2];
                sC[(t4p * 4 + k2) * SN + nn] = cv.a[k2];
            }
        }
        __syncthreads();

        // ---- scan phase over TBUF timesteps ----
        #pragma unroll 4
        for (int t4 = 0; t4 < TBUF; t4 += 4) {
            F4 d4, x4;
            d4.v = *(const float4*)(dp + tbase + t4);   // broadcast within seq group
            x4.v = *(const float4*)(xp + tbase + t4);

            #pragma unroll
            for (int k = 0; k < 4; ++k) {
                const float dt  = d4.a[k];
                const float dxv = dt * x4.a[k];
                const float e   = ex2f(dt * Apn);
                const float bb  = sB[(t4 + k) * SN + n];
                const float cc  = sC[(t4 + k) * SN + n];
                h = fmaf(e, h, dxv * bb);
                float p = h * cc;
                // reduce over 16 state lanes
                p += __shfl_xor_sync(0xffffffffu, p, 1);
                p += __shfl_xor_sync(0xffffffffu, p, 2);
                p += __shfl_xor_sync(0xffffffffu, p, 4);
                p += __shfl_xor_sync(0xffffffffu, p, 8);
                if (n == 0) ybuf[yrow][t4 + k] = p;
            }
        }
        __syncwarp();

        // ---- epilogue: out = (y + x*D) * silu(z), one float4 per lane ----
        {
            const int tt = tbase + n * 4;     // lane covers 4 timesteps of its seq
            F4 y4, xx4, zz4, o4;
            y4.v  = *(const float4*)&ybuf[yrow][n * 4];
            xx4.v = *(const float4*)(xp + tt);
            zz4.v = *(const float4*)(zp + tt);
            #pragma unroll
            for (int k = 0; k < 4; ++k) {
                const float zv  = zz4.a[k];
                const float sig = rcpf(1.f + ex2f(zv * (-LOG2E)));
                const float yv  = fmaf(xx4.a[k], Dd, y4.a[k]);
                o4.a[k] = yv * zv * sig;
            }
            *(float4*)(op + tt) = o4.v;
        }
        __syncthreads();   // protect sB/sC (and ybuf) before next tile
    }
}

extern "C" void kernel_launch(void* const* d_in, const int* in_sizes, int n_in,
                              void* d_out, int out_size)
{
    const float* x     = (const float*)d_in[0];
    const float* delta = (const float*)d_in[1];
    const float* A     = (const float*)d_in[2];
    const float* Bm    = (const float*)d_in[3];
    const float* Cm    = (const float*)d_in[4];
    const float* Dv    = (const float*)d_in[5];
    const float* z     = (const float*)d_in[6];
    float* out = (float*)d_out;

    ssm_scan_kernel<<<NBLOCKS, THREADS>>>(x, delta, A, Bm, Cm, Dv, z, out);
}

// round 11
// speedup vs baseline: 1.5110x; 1.0134x over previous
#include <cuda_runtime.h>
#include <cstdint>

// SSM selective scan: Bsz=2, Dm=1536, L=2048, N=16 (fp32).
// R5 mapping: 1 lane per (seq, n): 16 lanes/sequence, 2 sequences/warp,
// 1536 warps total. B/C staged block-wide through smem (coalesced LDG ->
// conflict-free LDS), y buffered in smem, fused (y+x*D)*silu(z) epilogue
// per TBUF tile.

#define LOG2E 1.4426950408889634f

static constexpr int Bsz = 2;
static constexpr int Dm  = 1536;
static constexpr int L   = 2048;
static constexpr int Nst = 16;

static constexpr int TBUF = 64;                 // timesteps per tile
static constexpr int SN   = 17;                 // smem tile row stride (banks)
static constexpr int WARPS_PER_BLOCK = 4;
static constexpr int THREADS = WARPS_PER_BLOCK * 32;   // 128
static constexpr int SEQ_PER_BLOCK = WARPS_PER_BLOCK * 2;  // 8
static constexpr int NSEQ = Bsz * Dm;                      // 3072
static constexpr int NBLOCKS = NSEQ / SEQ_PER_BLOCK;       // 384

__device__ __forceinline__ float ex2f(float v) {
    float r;
    asm("ex2.approx.ftz.f32 %0, %1;" : "=f"(r) : "f"(v));
    return r;
}
__device__ __forceinline__ float rcpf(float v) {
    float r;
    asm("rcp.approx.ftz.f32 %0, %1;" : "=f"(r) : "f"(v));
    return r;
}

union F4 { float4 v; float a[4]; };

__global__ __launch_bounds__(THREADS) void ssm_scan_kernel(
    const float* __restrict__ x,
    const float* __restrict__ delta,
    const float* __restrict__ A,
    const float* __restrict__ Bm,
    const float* __restrict__ Cm,
    const float* __restrict__ Dv,
    const float* __restrict__ z,
    float* __restrict__ out)
{
    __shared__ float sB[TBUF * SN];                     // [t][n], stride 17
    __shared__ float sC[TBUF * SN];
    __shared__ float ybuf[SEQ_PER_BLOCK][TBUF + 4];     // rows 16B-aligned

    const int tid  = threadIdx.x;
    const int warp = tid >> 5;
    const int lane = tid & 31;
    const int sg   = lane >> 4;      // sequence within warp (0/1)
    const int n    = lane & 15;      // state index

    const int seqBlock = blockIdx.x * SEQ_PER_BLOCK;
    const int seq = seqBlock + warp * 2 + sg;  // 0..3071
    const int b   = seq / Dm;                  // same for whole block (8 | 1536)
    const int d   = seq % Dm;
    const int yrow = warp * 2 + sg;

    const size_t rowOff = ((size_t)b * Dm + d) * L;
    const float* xp = x     + rowOff;
    const float* dp = delta + rowOff;
    const float* zp = z     + rowOff;
    float*       op = out   + rowOff;

    const float* Bg = Bm + (size_t)b * Nst * L;
    const float* Cg = Cm + (size_t)b * Nst * L;

    // Pre-scale A by log2(e): exp(delta*A) = ex2(delta*Apre)
    const float Apn = A[d * Nst + n] * LOG2E;
    const float Dd  = Dv[d];

    float h = 0.f;

    for (int tbase = 0; tbase < L; tbase += TBUF) {
        // ---- stage B/C tile [TBUF t x 16 n] into smem, coalesced ----
        #pragma unroll
        for (int i = 0; i < 2; ++i) {
            const int f4   = tid + i * THREADS;   // 0..255
            const int nn   = f4 >> 4;             // 0..15
            const int t4p  = f4 & 15;             // 0..15 (float4 within row)
            F4 bv, cv;
            bv.v = *(const float4*)(Bg + (size_t)nn * L + tbase + t4p * 4);
            cv.v = *(const float4*)(Cg + (size_t)nn * L + tbase + t4p * 4);
            #pragma unroll
            for (int k2 = 0; k2 < 4; ++k2) {
                sB[(t4p * 4 + k2) * SN + nn] = bv.a[k2];
                sC[(t4p * 4 + k2) * SN + nn] = cv.a[k2];
            }
        }
        __syncthreads();

        // ---- scan phase over TBUF timesteps ----
        #pragma unroll 4
        for (int t4 = 0; t4 < TBUF; t4 += 4) {
            F4 d4, x4;
            d4.v = *(const float4*)(dp + tbase + t4);   // broadcast within seq group
            x4.v = *(const float4*)(xp + tbase + t4);

            #pragma unroll
            for (int k = 0; k < 4; ++k) {
                const float dt  = d4.a[k];
                const float dxv = dt * x4.a[k];
                const float e   = ex2f(dt * Apn);
                const float bb  = sB[(t4 + k) * SN + n];
                const float cc  = sC[(t4 + k) * SN + n];
                h = fmaf(e, h, dxv * bb);
                float p = h * cc;
                // reduce over 16 state lanes
                p += __shfl_xor_sync(0xffffffffu, p, 1);
                p += __shfl_xor_sync(0xffffffffu, p, 2);
                p += __shfl_xor_sync(0xffffffffu, p, 4);
                p += __shfl_xor_sync(0xffffffffu, p, 8);
                if (n == 0) ybuf[yrow][t4 + k] = p;
            }
        }
        __syncwarp();

        // ---- epilogue: out = (y + x*D) * silu(z), one float4 per lane ----
        {
            const int tt = tbase + n * 4;     // lane covers 4 timesteps of its seq
            F4 y4, xx4, zz4, o4;
            y4.v  = *(const float4*)&ybuf[yrow][n * 4];
            xx4.v = *(const float4*)(xp + tt);
            zz4.v = *(const float4*)(zp + tt);
            #pragma unroll
            for (int k = 0; k < 4; ++k) {
                const float zv  = zz4.a[k];
                const float sig = rcpf(1.f + ex2f(zv * (-LOG2E)));
                const float yv  = fmaf(xx4.a[k], Dd, y4.a[k]);
                o4.a[k] = yv * zv * sig;
            }
            *(float4*)(op + tt) = o4.v;
        }
        __syncthreads();   // protect sB/sC (and ybuf) before next tile
    }
}

extern "C" void kernel_launch(void* const* d_in, const int* in_sizes, int n_in,
                              void* d_out, int out_size)
{
    const float* x     = (const float*)d_in[0];
    const float* delta = (const float*)d_in[1];
    const float* A     = (const float*)d_in[2];
    const float* Bm    = (const float*)d_in[3];
    const float* Cm    = (const float*)d_in[4];
    const float* Dv    = (const float*)d_in[5];
    const float* z     = (const float*)d_in[6];
    float* out = (float*)d_out;

    ssm_scan_kernel<<<NBLOCKS, THREADS>>>(x, delta, A, Bm, Cm, Dv, z, out);
}